// round 4
// baseline (speedup 1.0000x reference)
#include <cuda_runtime.h>
#include <cstddef>

// MultiLayerLSTM: T=1024, B=64, C=256, H=512, 2 layers, fp32.
// Persistent kernel (128 CTAs x 512 threads), SMEM-resident weights,
// f32x2 packed FMA, 8m x 4n x 16kg thread tile, chunked double-buffered
// activation staging, and a split grid barrier: arrive right after the h
// write, wait deferred until after the (dependency-free) x-part chunks.

#define T_    1024
#define B_    64
#define C_    256
#define H_    512
#define GRID_ 128
#define NTHR_ 512
#define KC_   64          // k per staged chunk
#define KP_   32          // k-pairs per chunk

// ---- shared memory layout (float offsets) ----
#define OFF_W   0
#define SZ_W    (16 * 1028)          // 16 gate rows x K(<=1024), f32x2 row stride 514
#define OFF_A0  (OFF_W + SZ_W)
#define SZ_A    (KP_ * 65 * 2)       // 32 k-pairs x 65 f32x2 (64 m + 1 pad)
#define OFF_A1  (OFF_A0 + SZ_A)
#define OFF_P   (OFF_A1 + SZ_A)
#define SZ_P    (1024 * 18)          // partials: 1024 outputs x 16 kgroups, stride 18
#define OFF_G   (OFF_P + SZ_P)
#define SZ_G    (16 * 65)
#define OFF_C   (OFF_G + SZ_G)
#define SZ_C    (4 * 65)
#define OFF_H   (OFF_C + SZ_C)
#define SZ_H    256
#define OFF_B   (OFF_H + SZ_H)
#define SMEM_FLOATS (OFF_B + 16)
#define SMEM_BYTES  (SMEM_FLOATS * 4)

static __device__ float g_y0[(size_t)T_ * B_ * H_];   // layer-0 outputs (128 MB scratch)
static __device__ int   g_bar;

__global__ void reset_kernel() {
    if (threadIdx.x == 0) g_bar = 0;
}

__device__ __forceinline__ void fma2(unsigned long long& d, unsigned long long a,
                                     unsigned long long b) {
    asm("fma.rn.f32x2 %0, %1, %2, %0;" : "+l"(d) : "l"(a), "l"(b));
}
__device__ __forceinline__ float sigf(float v) { return 1.0f / (1.0f + __expf(-v)); }

extern __shared__ float sm[];

__global__ void __launch_bounds__(NTHR_, 1) lstm_kernel(
    const float* __restrict__ x,
    const float* __restrict__ h00, const float* __restrict__ c00,
    const float* __restrict__ h01, const float* __restrict__ c01,
    const float* __restrict__ Wih0, const float* __restrict__ Whh0,
    const float* __restrict__ bih0, const float* __restrict__ bhh0,
    const float* __restrict__ Wih1, const float* __restrict__ Whh1,
    const float* __restrict__ bih1, const float* __restrict__ bhh1,
    float* out)
{
    const int tid = threadIdx.x;
    const int bid = blockIdx.x;
    const int j0  = bid * 4;           // first hidden unit owned by this CTA
    const int kg  = tid & 15;          // k-group (16-way k split)
    const int mg  = (tid >> 4) & 7;    // m-group (8 groups of 8 batch rows)
    const int ng  = tid >> 7;          // n-group (4 groups of 4 gate rows)

    float* Wsf   = sm + OFF_W;
    float* AbufA = sm + OFF_A0;
    float* AbufB = sm + OFF_A1;
    float* Pp    = sm + OFF_P;
    float* Gr    = sm + OFF_G;
    float* Cs    = sm + OFF_C;
    float* Hs    = sm + OFF_H;
    float* Bs    = sm + OFF_B;

    float* yout = out;
    float* h1f  = out + (size_t)T_ * B_ * H_;
    float* c1f  = h1f + B_ * H_;
    float* h2f  = c1f + B_ * H_;
    float* c2f  = h2f + B_ * H_;

    for (int phase = 0; phase < 2; phase++) {
        const int KX  = (phase == 0) ? C_ : H_;
        const int K   = KX + H_;
        const int NCH = K / KC_;          // 12 or 16 chunks
        const int XCH = KX / KC_;         // 4 or 8 chunks sourced from x-part
        const float* Wx    = (phase == 0) ? Wih0 : Wih1;
        const float* Wh    = (phase == 0) ? Whh0 : Whh1;
        const float* bi    = (phase == 0) ? bih0 : bih1;
        const float* bh    = (phase == 0) ? bhh0 : bhh1;
        const float* hinit = (phase == 0) ? h00 : h01;
        const float* cinit = (phase == 0) ? c00 : c01;
        float* hdst = (phase == 0) ? g_y0 : yout;
        float* hTd  = (phase == 0) ? h1f : h2f;
        float* cTd  = (phase == 0) ? c1f : c2f;
        const int arr_base = phase * T_;   // arrivals completed before this phase

        // ---- load weight slice [16 rows][K] = [Wx | Wh] into SMEM ----
        for (int idx = tid; idx < 16 * K; idx += NTHR_) {
            const int n = idx / K, k = idx - n * K;
            const int gr = (n >> 2) * H_ + j0 + (n & 3);
            const float v = (k < KX) ? Wx[(size_t)gr * KX + k]
                                     : Wh[(size_t)gr * H_ + (k - KX)];
            Wsf[n * 1028 + k] = v;
        }
        if (tid < 16) {
            const int gr = (tid >> 2) * H_ + j0 + (tid & 3);
            Bs[tid] = bi[gr] + bh[gr];
        }
        if (tid < 256) {
            const int jj = tid >> 6, m = tid & 63;
            Cs[jj * 65 + m] = cinit[m * H_ + j0 + jj];
        }
        __syncthreads();

        // phase-entry: all previous-phase h writes (g_y0) must be visible
        if (tid == 0) {
            const int target = arr_base * GRID_;
            while (*((volatile int*)&g_bar) < target) { }
            __threadfence();
        }
        __syncthreads();

        for (int t = 0; t < T_; t++) {
            const float* hprev = (t == 0) ? hinit : (hdst + (size_t)(t - 1) * B_ * H_);
            const float* xsrc  = (phase == 0) ? (x + (size_t)t * B_ * C_)
                                              : (g_y0 + (size_t)t * B_ * H_);
            const int xrs = (phase == 0) ? C_ : H_;

            unsigned long long acc[32];
            #pragma unroll
            for (int i = 0; i < 32; i++) acc[i] = 0ull;

            // ======== x-part: chunks [0, XCH) — no cross-CTA dependency ========
            // stage chunk 0
            {
                float4 v[2];
                #pragma unroll
                for (int it = 0; it < 2; it++) {
                    const int s = it * NTHR_ + tid;
                    const int k4 = s & 15, m = s >> 4;
                    v[it] = *(const float4*)(xsrc + (size_t)m * xrs + k4 * 4);
                }
                float2* b2 = (float2*)AbufA;
                #pragma unroll
                for (int it = 0; it < 2; it++) {
                    const int s = it * NTHR_ + tid;
                    const int k4 = s & 15, m = s >> 4;
                    b2[(2 * k4) * 65 + m]     = make_float2(v[it].x, v[it].y);
                    b2[(2 * k4 + 1) * 65 + m] = make_float2(v[it].z, v[it].w);
                }
            }

            for (int half = 0; half < 2; half++) {
                const int cfirst = half ? XCH : 0;
                const int clast  = half ? (NCH - 1) : (XCH - 1);

                if (half) {
                    // barrier wait for h[t-1] (deferred past x-part compute)
                    if (tid == 0) {
                        const int target = (arr_base + t) * GRID_;
                        while (*((volatile int*)&g_bar) < target) { }
                        __threadfence();
                    }
                    __syncthreads();
                    // stage first h chunk
                    float4 v[2];
                    #pragma unroll
                    for (int it = 0; it < 2; it++) {
                        const int s = it * NTHR_ + tid;
                        const int k4 = s & 15, m = s >> 4;
                        v[it] = *(const float4*)(hprev + (size_t)m * H_ + k4 * 4);
                    }
                    float2* b2 = (float2*)((cfirst & 1) ? AbufB : AbufA);
                    #pragma unroll
                    for (int it = 0; it < 2; it++) {
                        const int s = it * NTHR_ + tid;
                        const int k4 = s & 15, m = s >> 4;
                        b2[(2 * k4) * 65 + m]     = make_float2(v[it].x, v[it].y);
                        b2[(2 * k4 + 1) * 65 + m] = make_float2(v[it].z, v[it].w);
                    }
                }

                for (int c = cfirst; c <= clast; c++) {
                    __syncthreads();   // buf[c&1] ready, buf[(c+1)&1] free

                    // prefetch chunk c+1 (within this half only)
                    float4 v[2];
                    const bool pf = (c + 1 <= clast);
                    if (pf) {
                        const int cn = c + 1;
                        const float* src; int rs, col;
                        if (cn < XCH) { src = xsrc;  rs = xrs; col = cn * KC_; }
                        else          { src = hprev; rs = H_;  col = (cn - XCH) * KC_; }
                        #pragma unroll
                        for (int it = 0; it < 2; it++) {
                            const int s = it * NTHR_ + tid;
                            const int k4 = s & 15, m = s >> 4;
                            v[it] = *(const float4*)(src + (size_t)m * rs + col + k4 * 4);
                        }
                    }

                    // ---- compute: 32 k-pairs in chunk, 2 per thread ----
                    {
                        const unsigned long long* Ab =
                            (const unsigned long long*)((c & 1) ? AbufB : AbufA);
                        const unsigned long long* Wp =
                            (const unsigned long long*)Wsf;   // row stride 514 f32x2
                        #pragma unroll
                        for (int i = 0; i < 2; i++) {
                            const int kp = i * 16 + kg;
                            const unsigned long long* Ar = Ab + kp * 65 + mg * 8;
                            unsigned long long a0 = Ar[0], a1 = Ar[1], a2 = Ar[2], a3 = Ar[3];
                            unsigned long long a4 = Ar[4], a5 = Ar[5], a6 = Ar[6], a7 = Ar[7];
                            const unsigned long long* Wr = Wp + (ng * 4) * 514 + c * KP_ + kp;
                            unsigned long long w0 = Wr[0 * 514], w1 = Wr[1 * 514];
                            unsigned long long w2 = Wr[2 * 514], w3 = Wr[3 * 514];
                            fma2(acc[0 * 4 + 0], a0, w0); fma2(acc[1 * 4 + 0], a1, w0);
                            fma2(acc[2 * 4 + 0], a2, w0); fma2(acc[3 * 4 + 0], a3, w0);
                            fma2(acc[4 * 4 + 0], a4, w0); fma2(acc[5 * 4 + 0], a5, w0);
                            fma2(acc[6 * 4 + 0], a6, w0); fma2(acc[7 * 4 + 0], a7, w0);
                            fma2(acc[0 * 4 + 1], a0, w1); fma2(acc[1 * 4 + 1], a1, w1);
                            fma2(acc[2 * 4 + 1], a2, w1); fma2(acc[3 * 4 + 1], a3, w1);
                            fma2(acc[4 * 4 + 1], a4, w1); fma2(acc[5 * 4 + 1], a5, w1);
                            fma2(acc[6 * 4 + 1], a6, w1); fma2(acc[7 * 4 + 1], a7, w1);
                            fma2(acc[0 * 4 + 2], a0, w2); fma2(acc[1 * 4 + 2], a1, w2);
                            fma2(acc[2 * 4 + 2], a2, w2); fma2(acc[3 * 4 + 2], a3, w2);
                            fma2(acc[4 * 4 + 2], a4, w2); fma2(acc[5 * 4 + 2], a5, w2);
                            fma2(acc[6 * 4 + 2], a6, w2); fma2(acc[7 * 4 + 2], a7, w2);
                            fma2(acc[0 * 4 + 3], a0, w3); fma2(acc[1 * 4 + 3], a1, w3);
                            fma2(acc[2 * 4 + 3], a2, w3); fma2(acc[3 * 4 + 3], a3, w3);
                            fma2(acc[4 * 4 + 3], a4, w3); fma2(acc[5 * 4 + 3], a5, w3);
                            fma2(acc[6 * 4 + 3], a6, w3); fma2(acc[7 * 4 + 3], a7, w3);
                        }
                    }

                    // store prefetched chunk into the other buffer
                    if (pf) {
                        float2* b2 = (float2*)((c & 1) ? AbufA : AbufB);
                        #pragma unroll
                        for (int it = 0; it < 2; it++) {
                            const int s = it * NTHR_ + tid;
                            const int k4 = s & 15, m = s >> 4;
                            b2[(2 * k4) * 65 + m]     = make_float2(v[it].x, v[it].y);
                            b2[(2 * k4 + 1) * 65 + m] = make_float2(v[it].z, v[it].w);
                        }
                    }
                }
            }
            __syncthreads();

            // ---- fold f32x2 lanes, write partials ----
            #pragma unroll
            for (int mm = 0; mm < 8; mm++)
                #pragma unroll
                for (int nn = 0; nn < 4; nn++) {
                    const unsigned long long a = acc[mm * 4 + nn];
                    const float lo = __uint_as_float((unsigned)(a & 0xffffffffull));
                    const float hi = __uint_as_float((unsigned)(a >> 32));
                    const int n = ng * 4 + nn;
                    const int m = mg * 8 + mm;
                    Pp[(n * 64 + m) * 18 + kg] = lo + hi;
                }
            __syncthreads();

            // ---- reduce 16 k-groups + bias ----
            #pragma unroll
            for (int r = 0; r < 2; r++) {
                const int slot = r * NTHR_ + tid;
                const int n = slot >> 6, m = slot & 63;
                float s = Bs[n];
                #pragma unroll
                for (int q = 0; q < 16; q++) s += Pp[slot * 18 + q];
                Gr[n * 65 + m] = s;
            }
            __syncthreads();

            // ---- pointwise: gates -> c, h ----
            if (tid < 256) {
                const int jj = tid >> 6, m = tid & 63;
                const float gi = sigf(Gr[jj * 65 + m]);
                const float gf = sigf(Gr[(4 + jj) * 65 + m]);
                const float gc = tanhf(Gr[(8 + jj) * 65 + m]);
                const float go = sigf(Gr[(12 + jj) * 65 + m]);
                const float cv = gf * Cs[jj * 65 + m] + gi * gc;
                Cs[jj * 65 + m] = cv;
                const float hv = go * tanhf(cv);
                Hs[m * 4 + jj] = hv;
                if (t == T_ - 1) cTd[(size_t)m * H_ + j0 + jj] = cv;
            }
            __syncthreads();

            // ---- write h slice to global, then arrive (no wait here) ----
            if (tid < 64) {
                const float4 hv = *(const float4*)&Hs[tid * 4];
                *(float4*)(hdst + (size_t)t * B_ * H_ + (size_t)tid * H_ + j0) = hv;
                if (t == T_ - 1)
                    *(float4*)(hTd + (size_t)tid * H_ + j0) = hv;
                __threadfence();   // order h STG before the arrival below
            }
            __syncthreads();
            if (tid == 0) atomicAdd(&g_bar, 1);
        }
    }
}

extern "C" void kernel_launch(void* const* d_in, const int* in_sizes, int n_in,
                              void* d_out, int out_size) {
    (void)in_sizes; (void)n_in; (void)out_size;
    cudaFuncSetAttribute(lstm_kernel, cudaFuncAttributeMaxDynamicSharedMemorySize,
                         SMEM_BYTES);
    reset_kernel<<<1, 32>>>();
    lstm_kernel<<<GRID_, NTHR_, SMEM_BYTES>>>(
        (const float*)d_in[0],
        (const float*)d_in[1], (const float*)d_in[2],
        (const float*)d_in[3], (const float*)d_in[4],
        (const float*)d_in[5], (const float*)d_in[6],
        (const float*)d_in[7], (const float*)d_in[8],
        (const float*)d_in[9], (const float*)d_in[10],
        (const float*)d_in[11], (const float*)d_in[12],
        (float*)d_out);
}

// round 5
// speedup vs baseline: 1.6479x; 1.6479x over previous
#include <cuda_runtime.h>
#include <cstddef>

// MultiLayerLSTM: T=1024, B=64, C=256, H=512, fp32.
// Wavefront persistent kernel: 64 CTAs run layer0 step s while 64 CTAs run
// layer1 step s-1  -> 1025 supersteps instead of 2048.
// Per CTA: 8 hidden units (32 gate rows), 256 threads, 8m x 8n x 8kg tile,
// f32x2 packed FMA, SMEM-resident weights (loaded once), split 8-counter
// grid barrier, partials aliased over the dead activation buffers.

#define T_    1024
#define B_    64
#define C_    256
#define H_    512
#define GRID_ 128
#define NTHR_ 256

// ---- shared memory layout (float offsets) ----
#define OFF_W   0
#define SZ_W    (32 * 1028)              // 32 gate rows x K(<=1024), pad to 1028
#define OFF_A0  (OFF_W + SZ_W)
#define ABUF_   4160                      // 32 k-pairs x 65 f32x2
#define OFF_A1  (OFF_A0 + ABUF_)
#define OFF_P   OFF_A0                    // partials alias A buffers (disjoint in time)
#define SZ_P    (2048 * 9)                // 32n x 64m outputs x 8 kgroups, stride 9
#define OFF_G   (OFF_P + SZ_P)
#define SZ_G    (32 * 65)
#define OFF_C   (OFF_G + SZ_G)
#define SZ_C    (8 * 65)
#define OFF_H   (OFF_C + SZ_C)
#define SZ_H    512
#define OFF_B   (OFF_H + SZ_H)
#define SMEM_FLOATS (OFF_B + 32)
#define SMEM_BYTES  (SMEM_FLOATS * 4)     // ~217.9 KB

static __device__ float g_y0[(size_t)T_ * B_ * H_];   // layer-0 outputs (128 MB)
static __device__ int   g_bars[8 * 32];               // 8 counters, 128B apart

__global__ void reset_kernel() {
    if (threadIdx.x < 8) g_bars[threadIdx.x * 32] = 0;
}

__device__ __forceinline__ void fma2(unsigned long long& d, unsigned long long a,
                                     unsigned long long b) {
    asm("fma.rn.f32x2 %0, %1, %2, %0;" : "+l"(d) : "l"(a), "l"(b));
}
__device__ __forceinline__ float sigf(float v) { return 1.0f / (1.0f + __expf(-v)); }

extern __shared__ float sm[];

// One LSTM timestep for this CTA's 8 hidden units.
// SPLIT = chunk index before which we wait on the grid barrier.
__device__ __forceinline__ void lstm_step(
    int tid, int j0, int group,
    const float* __restrict__ xsrc, int xrs,
    const float* __restrict__ hprev,
    int NCH, int XCH, int SPLIT, int wtarget,
    float* __restrict__ hrow, bool last,
    float* __restrict__ hTd, float* __restrict__ cTd)
{
    float* Wsf   = sm + OFF_W;
    float* AbufA = sm + OFF_A0;
    float* AbufB = sm + OFF_A1;
    float* Pp    = sm + OFF_P;
    float* Gr    = sm + OFF_G;
    float* Cs    = sm + OFF_C;
    float* Hs    = sm + OFF_H;
    float* Bs    = sm + OFF_B;

    const int kg = tid & 7;           // 8-way k split
    const int mg = (tid >> 3) & 7;    // 8 m-groups of 8 batch rows
    const int ng = tid >> 6;          // 4 n-groups of 8 gate rows

    unsigned long long acc[64];
    #pragma unroll
    for (int i = 0; i < 64; i++) acc[i] = 0ull;

    float4 v[4];
    #pragma unroll 1
    for (int c = 0; c < NCH; c++) {
        if (c == SPLIT) {
            // grid-barrier wait (8 threads poll 8 counters in parallel)
            if (tid < 8) {
                volatile int* p = (volatile int*)&g_bars[tid * 32];
                while (*p < wtarget) { }
                __threadfence();
            }
            __syncthreads();
        }
        if (c == SPLIT || c == 0) {
            // stage chunk c directly (not prefetched)
            const float* src; int rs, col;
            if (c < XCH) { src = xsrc;  rs = xrs; col = c * 64; }
            else         { src = hprev; rs = H_;  col = (c - XCH) * 64; }
            #pragma unroll
            for (int it = 0; it < 4; it++) {
                const int s = it * NTHR_ + tid;
                const int k4 = s & 15, m = s >> 4;
                v[it] = *(const float4*)(src + (size_t)m * rs + col + k4 * 4);
            }
            float2* b2 = (float2*)((c & 1) ? AbufB : AbufA);
            #pragma unroll
            for (int it = 0; it < 4; it++) {
                const int s = it * NTHR_ + tid;
                const int k4 = s & 15, m = s >> 4;
                b2[(2 * k4) * 65 + m]     = make_float2(v[it].x, v[it].y);
                b2[(2 * k4 + 1) * 65 + m] = make_float2(v[it].z, v[it].w);
            }
        }
        __syncthreads();   // staged buffer ready / other buffer free

        const bool pf = (c + 1 < NCH) && (c + 1 != SPLIT);
        if (pf) {
            const int cn = c + 1;
            const float* src; int rs, col;
            if (cn < XCH) { src = xsrc;  rs = xrs; col = cn * 64; }
            else          { src = hprev; rs = H_;  col = (cn - XCH) * 64; }
            #pragma unroll
            for (int it = 0; it < 4; it++) {
                const int s = it * NTHR_ + tid;
                const int k4 = s & 15, m = s >> 4;
                v[it] = *(const float4*)(src + (size_t)m * rs + col + k4 * 4);
            }
        }

        // ---- compute: 32 k-pairs, 4 per kg thread ----
        {
            const unsigned long long* Ab =
                (const unsigned long long*)((c & 1) ? AbufB : AbufA);
            const unsigned long long* Wp = (const unsigned long long*)Wsf; // stride 514
            #pragma unroll
            for (int i = 0; i < 4; i++) {
                const int kp = i * 8 + kg;
                const unsigned long long* Ar = Ab + kp * 65 + mg * 8;
                unsigned long long a[8];
                #pragma unroll
                for (int mm = 0; mm < 8; mm++) a[mm] = Ar[mm];
                const unsigned long long* Wr = Wp + (ng * 8) * 514 + c * 32 + kp;
                unsigned long long w[8];
                #pragma unroll
                for (int nn = 0; nn < 8; nn++) w[nn] = Wr[nn * 514];
                #pragma unroll
                for (int nn = 0; nn < 8; nn++)
                    #pragma unroll
                    for (int mm = 0; mm < 8; mm++)
                        fma2(acc[mm * 8 + nn], a[mm], w[nn]);
            }
        }

        if (pf) {
            float2* b2 = (float2*)((c & 1) ? AbufA : AbufB);
            #pragma unroll
            for (int it = 0; it < 4; it++) {
                const int s = it * NTHR_ + tid;
                const int k4 = s & 15, m = s >> 4;
                b2[(2 * k4) * 65 + m]     = make_float2(v[it].x, v[it].y);
                b2[(2 * k4 + 1) * 65 + m] = make_float2(v[it].z, v[it].w);
            }
        }
    }
    __syncthreads();

    // ---- fold f32x2 lanes, write partials (aliases A buffers) ----
    #pragma unroll
    for (int mm = 0; mm < 8; mm++)
        #pragma unroll
        for (int nn = 0; nn < 8; nn++) {
            const unsigned long long a = acc[mm * 8 + nn];
            const float lo = __uint_as_float((unsigned)(a & 0xffffffffull));
            const float hi = __uint_as_float((unsigned)(a >> 32));
            const int n = ng * 8 + nn;
            const int m = mg * 8 + mm;
            Pp[(n * 64 + m) * 9 + kg] = lo + hi;
        }
    __syncthreads();

    // ---- reduce 8 k-groups + bias: 2048 outputs, 8 per thread ----
    #pragma unroll
    for (int r = 0; r < 8; r++) {
        const int slot = r * NTHR_ + tid;
        const int n = slot >> 6, m = slot & 63;
        float s = Bs[n];
        #pragma unroll
        for (int q = 0; q < 8; q++) s += Pp[slot * 9 + q];
        Gr[n * 65 + m] = s;
    }
    __syncthreads();

    // ---- pointwise: 512 cells, 2 per thread ----
    {
        const int m = tid & 63;
        const int jb = tid >> 6;
        #pragma unroll
        for (int u = 0; u < 2; u++) {
            const int jj = jb + u * 4;
            const float gi = sigf(Gr[jj * 65 + m]);
            const float gf = sigf(Gr[(8 + jj) * 65 + m]);
            const float gc = tanhf(Gr[(16 + jj) * 65 + m]);
            const float go = sigf(Gr[(24 + jj) * 65 + m]);
            const float cv = gf * Cs[jj * 65 + m] + gi * gc;
            Cs[jj * 65 + m] = cv;
            Hs[m * 8 + jj] = go * tanhf(cv);
            if (last) cTd[(size_t)m * H_ + j0 + jj] = cv;
        }
    }
    __syncthreads();

    // ---- write h slice (64 m x 8 j) to global ----
    if (tid < 128) {
        const int m = tid >> 1, q = tid & 1;
        const float4 hv = *(const float4*)&Hs[m * 8 + q * 4];
        *(float4*)(hrow + (size_t)m * H_ + j0 + q * 4) = hv;
        if (last) *(float4*)(hTd + (size_t)m * H_ + j0 + q * 4) = hv;
        __threadfence();
    }
    __syncthreads();
    if (tid == 0) atomicAdd(&g_bars[group * 32], 1);
}

__global__ void __launch_bounds__(NTHR_, 1) lstm_kernel(
    const float* __restrict__ x,
    const float* __restrict__ h00, const float* __restrict__ c00,
    const float* __restrict__ h01, const float* __restrict__ c01,
    const float* __restrict__ Wih0, const float* __restrict__ Whh0,
    const float* __restrict__ bih0, const float* __restrict__ bhh0,
    const float* __restrict__ Wih1, const float* __restrict__ Whh1,
    const float* __restrict__ bih1, const float* __restrict__ bhh1,
    float* out)
{
    const int tid  = threadIdx.x;
    const int bid  = blockIdx.x;
    const int role = bid >> 6;           // 0: layer0 CTAs, 1: layer1 CTAs
    const int j0   = (bid & 63) * 8;     // 8 hidden units per CTA
    const int group = bid >> 4;          // 8 barrier counters, 16 CTAs each

    float* Wsf = sm + OFF_W;
    float* Cs  = sm + OFF_C;
    float* Bs  = sm + OFF_B;

    float* yout = out;
    float* h1f  = out + (size_t)T_ * B_ * H_;
    float* c1f  = h1f + B_ * H_;
    float* h2f  = c1f + B_ * H_;
    float* c2f  = h2f + B_ * H_;

    const int KX = (role == 0) ? C_ : H_;
    const int K  = KX + H_;
    const float* Wx    = (role == 0) ? Wih0 : Wih1;
    const float* Wh    = (role == 0) ? Whh0 : Whh1;
    const float* bi    = (role == 0) ? bih0 : bih1;
    const float* bh    = (role == 0) ? bhh0 : bhh1;
    const float* cinit = (role == 0) ? c00 : c01;

    // ---- one-time setup: weights [32 rows][K], bias, cell state ----
    for (int idx = tid; idx < 32 * K; idx += NTHR_) {
        const int n = idx / K, k = idx - n * K;
        const int gr = (n >> 3) * H_ + j0 + (n & 7);
        const float v = (k < KX) ? Wx[(size_t)gr * KX + k]
                                 : Wh[(size_t)gr * H_ + (k - KX)];
        Wsf[n * 1028 + k] = v;
    }
    if (tid < 32) {
        const int gr = (tid >> 3) * H_ + j0 + (tid & 7);
        Bs[tid] = bi[gr] + bh[gr];
    }
    {
        const int m = tid & 63, jb = tid >> 6;
        Cs[jb * 65 + m]       = cinit[(size_t)m * H_ + j0 + jb];
        Cs[(jb + 4) * 65 + m] = cinit[(size_t)m * H_ + j0 + jb + 4];
    }
    __syncthreads();

    // ---- wavefront: superstep s = layer0 step s  |  layer1 step s-1 ----
    for (int s = 0; s <= T_; s++) {
        if (role == 0) {
            if (s < T_) {
                const int t = s;
                lstm_step(tid, j0, group,
                          x + (size_t)t * B_ * C_, C_,
                          (t == 0) ? h00 : (g_y0 + (size_t)(t - 1) * B_ * H_),
                          /*NCH=*/12, /*XCH=*/4, /*SPLIT=*/4, /*wtarget=*/s * 16,
                          g_y0 + (size_t)t * B_ * H_, t == T_ - 1, h1f, c1f);
            } else {
                __syncthreads();
                if (tid == 0) atomicAdd(&g_bars[group * 32], 1);
            }
        } else {
            if (s >= 1) {
                const int t = s - 1;
                lstm_step(tid, j0, group,
                          g_y0 + (size_t)t * B_ * H_, H_,
                          (t == 0) ? h01 : (yout + (size_t)(t - 1) * B_ * H_),
                          /*NCH=*/16, /*XCH=*/8, /*SPLIT=*/0, /*wtarget=*/s * 16,
                          yout + (size_t)t * B_ * H_, t == T_ - 1, h2f, c2f);
            } else {
                __syncthreads();
                if (tid == 0) atomicAdd(&g_bars[group * 32], 1);
            }
        }
    }
}

extern "C" void kernel_launch(void* const* d_in, const int* in_sizes, int n_in,
                              void* d_out, int out_size) {
    (void)in_sizes; (void)n_in; (void)out_size;
    cudaFuncSetAttribute(lstm_kernel, cudaFuncAttributeMaxDynamicSharedMemorySize,
                         SMEM_BYTES);
    reset_kernel<<<1, 32>>>();
    lstm_kernel<<<GRID_, NTHR_, SMEM_BYTES>>>(
        (const float*)d_in[0],
        (const float*)d_in[1], (const float*)d_in[2],
        (const float*)d_in[3], (const float*)d_in[4],
        (const float*)d_in[5], (const float*)d_in[6],
        (const float*)d_in[7], (const float*)d_in[8],
        (const float*)d_in[9], (const float*)d_in[10],
        (const float*)d_in[11], (const float*)d_in[12],
        (float*)d_out);
}